// round 2
// baseline (speedup 1.0000x reference)
#include <cuda_runtime.h>
#include <cuda_bf16.h>
#include <math.h>

// ---------------------------------------------------------------------------
// TreeEncoder: quadtree encoder, depths 0..9, HIDDEN=EMB=128.
// Pipeline: posenc+in_proj -> top-down (pool + quadconv) -> emb + layernorm.
// All fp32. Three GEMMs share a 64x128-tile / 256-thread register-blocked core.
// ---------------------------------------------------------------------------

#define MAX_DEPTH 9
#define HIDDEN 128
#define TOTAL 349525          // sum 4^d, d=0..9
#define OFF9  87381           // offset of depth 9 (= sum 4^d, d=0..8)
#define XCOLS 48              // 40 real input cols, padded to 48

__constant__ int c_off[11] = {0,1,5,21,85,341,1365,5461,21845,87381,349525};

static const int h_off[11]  = {0,1,5,21,85,341,1365,5461,21845,87381,349525};
static const int h_size[10] = {1,4,16,64,256,1024,4096,16384,65536,262144};

// ---------------- static scratch (no runtime allocation) -------------------
__device__ float HBUF[TOTAL * 128];          // h after in_proj (+ pooling adds)
__device__ float HCBUF[OFF9 * 128];          // conv outputs, depths 1..8
__device__ float XBUF[TOTAL * XCOLS];        // padded pos-encoded inputs
__device__ float WT_IN[XCOLS * 128];         // in_proj_W^T, zero-padded rows
__device__ float WT_CONV[10 * 1152 * 128];   // conv_W^T  per depth (k-major)
__device__ float WT_EMB[10 * 128 * 128];     // emb_W^T per depth (k-major)

// ---------------- Morton helpers -------------------------------------------
__device__ __forceinline__ unsigned mi_interleave(unsigned x) {
    x &= 0xFFFFu;
    x = (x | (x << 8)) & 0x00FF00FFu;
    x = (x | (x << 4)) & 0x0F0F0F0Fu;
    x = (x | (x << 2)) & 0x33333333u;
    x = (x | (x << 1)) & 0x55555555u;
    return x;
}
__device__ __forceinline__ unsigned mi_deinterleave(unsigned x) {
    x &= 0x55555555u;
    x = (x | (x >> 1)) & 0x33333333u;
    x = (x | (x >> 2)) & 0x0F0F0F0Fu;
    x = (x | (x >> 4)) & 0x00FF00FFu;
    x = (x | (x >> 8)) & 0xFFFFu;
    return x;
}

// ---------------- weight transposition (runs each replay; trivial cost) ----
#define PREP_TOTAL (XCOLS*128 + 10*1152*128 + 10*128*128)

__global__ void prep_kernel(const float* __restrict__ in_proj_W,
                            const float* __restrict__ conv_W,
                            const float* __restrict__ emb_W) {
    int i = blockIdx.x * blockDim.x + threadIdx.x;
    if (i < XCOLS * 128) {
        int c = i / 128, j = i % 128;
        WT_IN[i] = (c < 40) ? in_proj_W[j * 40 + c] : 0.f;
        return;
    }
    i -= XCOLS * 128;
    if (i < 10 * 1152 * 128) {
        int d = i / (1152 * 128);
        int r = i % (1152 * 128);
        int k = r / 128, j = r % 128;
        WT_CONV[d * 1152 * 128 + r] = conv_W[(d * 128 + j) * 1152 + k];
        return;
    }
    i -= 10 * 1152 * 128;
    if (i < 10 * 128 * 128) {
        int d = i / 16384;
        int r = i % 16384;
        int c = r / 128, j = r % 128;
        WT_EMB[d * 16384 + r] = emb_W[(d * 128 + j) * 128 + c];
    }
}

// ---------------- positional encoding into XBUF ----------------------------
__global__ void posenc_kernel(const float* __restrict__ feats) {
    int i = blockIdx.x * blockDim.x + threadIdx.x;
    if (i >= TOTAL * XCOLS) return;
    int node = i / XCOLS, c = i % XCOLS;
    float v = 0.f;
    if (c < 40) {
        int d = 0;
        while (node >= c_off[d + 1]) d++;
        int local = node - c_off[d];
        if (c == 0) {
            v = feats[node];
        } else {
            unsigned ix = mi_deinterleave((unsigned)local);
            unsigned iy = mi_deinterleave((unsigned)local >> 1);
            float inv = 1.f / (float)(1 << d);
            float px = ((float)ix + 0.5f) * inv;
            float py = ((float)iy + 0.5f) * inv;
            float pd = (float)d * (1.f / 9.f);
            if (c == 1)      v = px;
            else if (c == 2) v = py;
            else if (c == 3) v = pd;
            else {
                int e = c - 4;
                int dim = e / 12, rem = e % 12;
                int f = rem % 6;
                float p = (dim == 0) ? px : (dim == 1) ? py : pd;
                float t = p * (float)(1 << f);        // ang / (2*pi)
                float tr = t - rintf(t);              // exact reduction, [-0.5,0.5]
                v = (rem >= 6) ? cospif(2.f * tr) : sinpif(2.f * tr);
            }
        }
    }
    XBUF[i] = v;
}

// ---------------- pooling: parent += mean of 4 Morton children -------------
__global__ void pool_kernel(int src_off, int dst_off, int Np, int srcIsHC) {
    int u = blockIdx.x * blockDim.x + threadIdx.x;
    if (u >= Np * 128) return;
    int p = u >> 7, c = u & 127;
    const float* s = (srcIsHC ? HCBUF : HBUF) + (size_t)(src_off + p * 4) * 128 + c;
    HBUF[(size_t)(dst_off + p) * 128 + c] += 0.25f * (s[0] + s[128] + s[256] + s[384]);
}

// ---------------- in_proj GEMM: X[N,48] @ WT_IN[48,128] + b -> HBUF --------
__global__ __launch_bounds__(256)
void inproj_gemm(const float* __restrict__ bias) {
    __shared__ float As[16][64];
    __shared__ float Bs[16][128];
    int t = threadIdx.x;
    int base = blockIdx.x * 64;
    int tc = t & 31, tr = t >> 5;
    int arow = t >> 2, acol = (t & 3) * 4;

    float acc[8][4];
#pragma unroll
    for (int ri = 0; ri < 8; ri++)
#pragma unroll
        for (int ji = 0; ji < 4; ji++) acc[ri][ji] = 0.f;

    for (int k0 = 0; k0 < XCOLS; k0 += 16) {
        int node = base + arow;
        float4 av = make_float4(0.f, 0.f, 0.f, 0.f);
        if (node < TOTAL)
            av = *reinterpret_cast<const float4*>(&XBUF[(size_t)node * XCOLS + k0 + acol]);
        As[acol + 0][arow] = av.x;
        As[acol + 1][arow] = av.y;
        As[acol + 2][arow] = av.z;
        As[acol + 3][arow] = av.w;
        const float4* bsrc = reinterpret_cast<const float4*>(&WT_IN[k0 * 128]);
        float4* bdst = reinterpret_cast<float4*>(&Bs[0][0]);
        bdst[t] = bsrc[t];
        bdst[t + 256] = bsrc[t + 256];
        __syncthreads();
#pragma unroll
        for (int kk = 0; kk < 16; kk++) {
            float4 b4 = *reinterpret_cast<const float4*>(&Bs[kk][tc * 4]);
            float4 a0 = *reinterpret_cast<const float4*>(&As[kk][tr * 8]);
            float4 a1 = *reinterpret_cast<const float4*>(&As[kk][tr * 8 + 4]);
            float a[8] = {a0.x, a0.y, a0.z, a0.w, a1.x, a1.y, a1.z, a1.w};
            float bb[4] = {b4.x, b4.y, b4.z, b4.w};
#pragma unroll
            for (int ri = 0; ri < 8; ri++)
#pragma unroll
                for (int ji = 0; ji < 4; ji++)
                    acc[ri][ji] = fmaf(a[ri], bb[ji], acc[ri][ji]);
        }
        __syncthreads();
    }
    float4 b4 = *reinterpret_cast<const float4*>(&bias[tc * 4]);
    float bb[4] = {b4.x, b4.y, b4.z, b4.w};
#pragma unroll
    for (int ri = 0; ri < 8; ri++) {
        int node = base + tr * 8 + ri;
        if (node < TOTAL) {
            float4 o;
            o.x = acc[ri][0] + bb[0];
            o.y = acc[ri][1] + bb[1];
            o.z = acc[ri][2] + bb[2];
            o.w = acc[ri][3] + bb[3];
            *reinterpret_cast<float4*>(&HBUF[(size_t)node * 128 + tc * 4]) = o;
        }
    }
}

// ---------------- quadconv: implicit GEMM with Morton 3x3 gather -----------
// out[n,j] = relu(b[j] + sum_m sum_c h[neigh(n,m),c] * W[j, m*128+c])
__global__ __launch_bounds__(256)
void conv_kernel(int depth, int off, int N, const float* __restrict__ conv_b) {
    __shared__ float As[16][64];
    __shared__ float Bs[16][128];
    __shared__ int nbs[64][9];
    int t = threadIdx.x;
    int base = blockIdx.x * 64;
    int res = 1 << depth;

    for (int e = t; e < 64 * 9; e += 256) {
        int r = e / 9, m = e % 9;
        int node = base + r;
        int val = -1;
        if (node < N) {
            unsigned ix = mi_deinterleave((unsigned)node);
            unsigned iy = mi_deinterleave((unsigned)node >> 1);
            int dx = m % 3 - 1, dy = m / 3 - 1;
            int nx = (int)ix + dx, ny = (int)iy + dy;
            if (nx >= 0 && nx < res && ny >= 0 && ny < res)
                val = (int)(mi_interleave((unsigned)nx) | (mi_interleave((unsigned)ny) << 1));
        }
        nbs[r][m] = val;
    }
    __syncthreads();

    int tc = t & 31, tr = t >> 5;
    int arow = t >> 2, acol = (t & 3) * 4;
    const float* Wt = WT_CONV + (size_t)depth * 1152 * 128;

    float acc[8][4];
#pragma unroll
    for (int ri = 0; ri < 8; ri++)
#pragma unroll
        for (int ji = 0; ji < 4; ji++) acc[ri][ji] = 0.f;

    for (int k0 = 0; k0 < 1152; k0 += 16) {
        int m = k0 >> 7;
        int c0 = k0 & 127;
        int nbi = nbs[arow][m];
        float4 av = make_float4(0.f, 0.f, 0.f, 0.f);
        if (nbi >= 0)
            av = *reinterpret_cast<const float4*>(&HBUF[(size_t)(off + nbi) * 128 + c0 + acol]);
        As[acol + 0][arow] = av.x;
        As[acol + 1][arow] = av.y;
        As[acol + 2][arow] = av.z;
        As[acol + 3][arow] = av.w;
        const float4* bsrc = reinterpret_cast<const float4*>(&Wt[(size_t)k0 * 128]);
        float4* bdst = reinterpret_cast<float4*>(&Bs[0][0]);
        bdst[t] = bsrc[t];
        bdst[t + 256] = bsrc[t + 256];
        __syncthreads();
#pragma unroll
        for (int kk = 0; kk < 16; kk++) {
            float4 b4 = *reinterpret_cast<const float4*>(&Bs[kk][tc * 4]);
            float4 a0 = *reinterpret_cast<const float4*>(&As[kk][tr * 8]);
            float4 a1 = *reinterpret_cast<const float4*>(&As[kk][tr * 8 + 4]);
            float a[8] = {a0.x, a0.y, a0.z, a0.w, a1.x, a1.y, a1.z, a1.w};
            float bb[4] = {b4.x, b4.y, b4.z, b4.w};
#pragma unroll
            for (int ri = 0; ri < 8; ri++)
#pragma unroll
                for (int ji = 0; ji < 4; ji++)
                    acc[ri][ji] = fmaf(a[ri], bb[ji], acc[ri][ji]);
        }
        __syncthreads();
    }
    float4 b4 = *reinterpret_cast<const float4*>(&conv_b[depth * 128 + tc * 4]);
    float bb[4] = {b4.x, b4.y, b4.z, b4.w};
#pragma unroll
    for (int ri = 0; ri < 8; ri++) {
        int node = base + tr * 8 + ri;
        if (node < N) {
            float4 o;
            o.x = fmaxf(acc[ri][0] + bb[0], 0.f);
            o.y = fmaxf(acc[ri][1] + bb[1], 0.f);
            o.z = fmaxf(acc[ri][2] + bb[2], 0.f);
            o.w = fmaxf(acc[ri][3] + bb[3], 0.f);
            *reinterpret_cast<float4*>(&HCBUF[(size_t)(off + node) * 128 + tc * 4]) = o;
        }
    }
}

// ---------------- emb GEMM + fused LayerNorm -------------------------------
__global__ __launch_bounds__(256)
void emb_kernel(int depth, int off, int N, int useHC,
                const float* __restrict__ emb_b,
                const float* __restrict__ ln_g,
                const float* __restrict__ ln_b,
                const float* __restrict__ gain_all,
                float* __restrict__ out) {
    __shared__ float As[16][64];
    __shared__ float Bs[16][128];
    int t = threadIdx.x;
    int base = blockIdx.x * 64;
    int tc = t & 31, tr = t >> 5;
    int arow = t >> 2, acol = (t & 3) * 4;
    const float* src = useHC ? HCBUF : HBUF;
    const float* Wt = WT_EMB + (size_t)depth * 16384;

    float acc[8][4];
#pragma unroll
    for (int ri = 0; ri < 8; ri++)
#pragma unroll
        for (int ji = 0; ji < 4; ji++) acc[ri][ji] = 0.f;

    for (int k0 = 0; k0 < 128; k0 += 16) {
        int node = base + arow;
        float4 av = make_float4(0.f, 0.f, 0.f, 0.f);
        if (node < N)
            av = *reinterpret_cast<const float4*>(&src[(size_t)(off + node) * 128 + k0 + acol]);
        As[acol + 0][arow] = av.x;
        As[acol + 1][arow] = av.y;
        As[acol + 2][arow] = av.z;
        As[acol + 3][arow] = av.w;
        const float4* bsrc = reinterpret_cast<const float4*>(&Wt[(size_t)k0 * 128]);
        float4* bdst = reinterpret_cast<float4*>(&Bs[0][0]);
        bdst[t] = bsrc[t];
        bdst[t + 256] = bsrc[t + 256];
        __syncthreads();
#pragma unroll
        for (int kk = 0; kk < 16; kk++) {
            float4 b4 = *reinterpret_cast<const float4*>(&Bs[kk][tc * 4]);
            float4 a0 = *reinterpret_cast<const float4*>(&As[kk][tr * 8]);
            float4 a1 = *reinterpret_cast<const float4*>(&As[kk][tr * 8 + 4]);
            float a[8] = {a0.x, a0.y, a0.z, a0.w, a1.x, a1.y, a1.z, a1.w};
            float bb[4] = {b4.x, b4.y, b4.z, b4.w};
#pragma unroll
            for (int ri = 0; ri < 8; ri++)
#pragma unroll
                for (int ji = 0; ji < 4; ji++)
                    acc[ri][ji] = fmaf(a[ri], bb[ji], acc[ri][ji]);
        }
        __syncthreads();
    }

    // epilogue: each warp (tr) owns 8 complete rows; LN via warp shuffles
    float4 eb4 = *reinterpret_cast<const float4*>(&emb_b[depth * 128 + tc * 4]);
    float4 lg4 = *reinterpret_cast<const float4*>(&ln_g[depth * 128 + tc * 4]);
    float4 lb4 = *reinterpret_cast<const float4*>(&ln_b[depth * 128 + tc * 4]);
    float g = gain_all[depth];
#pragma unroll
    for (int ri = 0; ri < 8; ri++) {
        float z0 = acc[ri][0] + eb4.x;
        float z1 = acc[ri][1] + eb4.y;
        float z2 = acc[ri][2] + eb4.z;
        float z3 = acc[ri][3] + eb4.w;
        float s = z0 + z1 + z2 + z3;
#pragma unroll
        for (int o = 16; o > 0; o >>= 1) s += __shfl_xor_sync(0xFFFFFFFFu, s, o);
        float mu = s * (1.f / 128.f);
        float d0 = z0 - mu, d1 = z1 - mu, d2 = z2 - mu, d3 = z3 - mu;
        float q = d0 * d0 + d1 * d1 + d2 * d2 + d3 * d3;
#pragma unroll
        for (int o = 16; o > 0; o >>= 1) q += __shfl_xor_sync(0xFFFFFFFFu, q, o);
        float rs = rsqrtf(q * (1.f / 128.f) + 1e-5f);
        int node = base + tr * 8 + ri;
        if (node < N) {
            float4 o4;
            o4.x = g * (d0 * rs * lg4.x + lb4.x);
            o4.y = g * (d1 * rs * lg4.y + lb4.y);
            o4.z = g * (d2 * rs * lg4.z + lb4.z);
            o4.w = g * (d3 * rs * lg4.w + lb4.w);
            *reinterpret_cast<float4*>(&out[(size_t)(off + node) * 128 + tc * 4]) = o4;
        }
    }
}

// ---------------------------------------------------------------------------
extern "C" void kernel_launch(void* const* d_in, const int* in_sizes, int n_in,
                              void* d_out, int out_size) {
    const float* feats     = (const float*)d_in[0];
    const float* in_proj_W = (const float*)d_in[1];
    const float* in_proj_b = (const float*)d_in[2];
    const float* conv_W    = (const float*)d_in[3];
    const float* conv_b    = (const float*)d_in[4];
    const float* emb_W     = (const float*)d_in[5];
    const float* emb_b     = (const float*)d_in[6];
    const float* ln_g      = (const float*)d_in[7];
    const float* ln_b      = (const float*)d_in[8];
    const float* gain      = (const float*)d_in[9];
    float* out = (float*)d_out;

    prep_kernel<<<(PREP_TOTAL + 255) / 256, 256>>>(in_proj_W, conv_W, emb_W);
    posenc_kernel<<<(TOTAL * XCOLS + 255) / 256, 256>>>(feats);
    inproj_gemm<<<(TOTAL + 63) / 64, 256>>>(in_proj_b);

    for (int d = MAX_DEPTH; d >= 1; d--) {
        int Np = h_size[d - 1];
        pool_kernel<<<(Np * 128 + 255) / 256, 256>>>(h_off[d], h_off[d - 1], Np,
                                                     (d == MAX_DEPTH) ? 0 : 1);
        if (d - 1 >= 1)
            conv_kernel<<<(h_size[d - 1] + 63) / 64, 256>>>(d - 1, h_off[d - 1],
                                                            h_size[d - 1], conv_b);
    }
    for (int d = 0; d <= MAX_DEPTH; d++) {
        int useHC = (d >= 1 && d <= 8) ? 1 : 0;
        emb_kernel<<<(h_size[d] + 63) / 64, 256>>>(d, h_off[d], h_size[d], useHC,
                                                   emb_b, ln_g, ln_b, gain, out);
    }
}